// round 1
// baseline (speedup 1.0000x reference)
#include <cuda_runtime.h>
#include <cstdint>
#include <cstddef>

// ---------------------------------------------------------------------------
// Problem constants
// ---------------------------------------------------------------------------
#define BATCH   256
#define SEQ     512
#define NIN     256
#define HID     256
#define G3      768          // 3*HID
#define LAYERS  2
#define ROWS    (BATCH*SEQ)  // 131072
#define RANKSUM 96           // 64 + 32

// ---------------------------------------------------------------------------
// Static device scratch (no cudaMalloc allowed)
// ---------------------------------------------------------------------------
__device__ float g_t_buf[(size_t)ROWS * RANKSUM];   //  50 MB  stage-1 of wx
__device__ float g_wx_buf[(size_t)ROWS * G3];       // 403 MB  wx (all t)
__device__ float g_x1[(size_t)ROWS * HID];          // 134 MB  layer-0 output
__device__ float g_P [LAYERS * NIN * RANKSUM];      // [Wd|Wo]
__device__ float g_Q [LAYERS * RANKSUM * G3];       // [Wdg;Wog]
__device__ float g_Pu[LAYERS * HID * RANKSUM];      // [Ud|Uo]
__device__ float g_Qu[LAYERS * RANKSUM * G3];       // [Udg;Uog]
__device__ float g_Ueff[LAYERS * HID * G3];         // dense recurrent weight
__device__ float g_h [2 * 16 * HID * 16];           // h double buffer [buf][grp][k][b]

// ---------------------------------------------------------------------------
// Pack kernel: concatenate low-rank factors
// ---------------------------------------------------------------------------
__global__ void pack_kernel(const float* __restrict__ Wd, const float* __restrict__ Wdg,
                            const float* __restrict__ Wo, const float* __restrict__ Wog,
                            const float* __restrict__ Ud, const float* __restrict__ Udg,
                            const float* __restrict__ Uo, const float* __restrict__ Uog)
{
    int idx = blockIdx.x * 256 + threadIdx.x;
    const int QN = LAYERS * RANKSUM * G3;   // 147456
    const int PN = LAYERS * NIN * RANKSUM;  // 49152
    if (idx < QN) {
        int l = idx / (RANKSUM * G3);
        int rem = idx - l * (RANKSUM * G3);
        int r = rem / G3, n = rem - r * G3;
        g_Q[idx]  = (r < 64) ? Wdg[(l*64 + r) * G3 + n] : Wog[(l*32 + (r-64)) * G3 + n];
        g_Qu[idx] = (r < 64) ? Udg[(l*64 + r) * G3 + n] : Uog[(l*32 + (r-64)) * G3 + n];
    }
    if (idx < PN) {
        int l = idx / (NIN * RANKSUM);
        int rem = idx - l * (NIN * RANKSUM);
        int k = rem / RANKSUM, j = rem - k * RANKSUM;
        g_P[idx]  = (j < 64) ? Wd[(l*NIN + k) * 64 + j] : Wo[(l*NIN + k) * 32 + (j-64)];
        g_Pu[idx] = (j < 64) ? Ud[(l*NIN + k) * 64 + j] : Uo[(l*NIN + k) * 32 + (j-64)];
    }
}

// ---------------------------------------------------------------------------
// Generic tiled fp32 GEMM: C[M,N] = A[M,K] @ B[K,N] (+ bias)
// BM=64, BN=64, BK=16, 256 threads, 4x4 microtile. M%64==0, K%16==0, N%4==0.
// ---------------------------------------------------------------------------
__global__ void __launch_bounds__(256)
gemm_tiled(const float* __restrict__ A, const float* __restrict__ B,
           const float* __restrict__ bias, float* __restrict__ C,
           int M, int N, int K)
{
    __shared__ float As[16][64];
    __shared__ float Bs[16][68];

    const int tid = threadIdx.x;
    const int tm = tid >> 4, tn = tid & 15;
    const size_t bm = (size_t)blockIdx.x * 64;
    const int bn = blockIdx.y * 64;

    const int ar = tid >> 2, ak = (tid & 3) << 2;
    const int brow = tid >> 4, bcol = (tid & 15) << 2;

    float acc[4][4];
#pragma unroll
    for (int i = 0; i < 4; ++i)
#pragma unroll
        for (int j = 0; j < 4; ++j) acc[i][j] = 0.f;

    for (int k0 = 0; k0 < K; k0 += 16) {
        float4 av = *(const float4*)(A + (bm + ar) * (size_t)K + k0 + ak);
        As[ak + 0][ar] = av.x; As[ak + 1][ar] = av.y;
        As[ak + 2][ar] = av.z; As[ak + 3][ar] = av.w;

        float4 bv = make_float4(0.f, 0.f, 0.f, 0.f);
        if (bn + bcol < N)
            bv = *(const float4*)(B + (size_t)(k0 + brow) * N + bn + bcol);
        *(float4*)&Bs[brow][bcol] = bv;
        __syncthreads();

#pragma unroll
        for (int k = 0; k < 16; ++k) {
            float4 a = *(const float4*)&As[k][tm << 2];
            float4 b = *(const float4*)&Bs[k][tn << 2];
            acc[0][0] = fmaf(a.x, b.x, acc[0][0]); acc[0][1] = fmaf(a.x, b.y, acc[0][1]);
            acc[0][2] = fmaf(a.x, b.z, acc[0][2]); acc[0][3] = fmaf(a.x, b.w, acc[0][3]);
            acc[1][0] = fmaf(a.y, b.x, acc[1][0]); acc[1][1] = fmaf(a.y, b.y, acc[1][1]);
            acc[1][2] = fmaf(a.y, b.z, acc[1][2]); acc[1][3] = fmaf(a.y, b.w, acc[1][3]);
            acc[2][0] = fmaf(a.z, b.x, acc[2][0]); acc[2][1] = fmaf(a.z, b.y, acc[2][1]);
            acc[2][2] = fmaf(a.z, b.z, acc[2][2]); acc[2][3] = fmaf(a.z, b.w, acc[2][3]);
            acc[3][0] = fmaf(a.w, b.x, acc[3][0]); acc[3][1] = fmaf(a.w, b.y, acc[3][1]);
            acc[3][2] = fmaf(a.w, b.z, acc[3][2]); acc[3][3] = fmaf(a.w, b.w, acc[3][3]);
        }
        __syncthreads();
    }

#pragma unroll
    for (int i = 0; i < 4; ++i) {
        size_t row = bm + (tm << 2) + i;
#pragma unroll
        for (int j = 0; j < 4; ++j) {
            int colj = bn + (tn << 2) + j;
            if (colj < N) {
                float v = acc[i][j];
                if (bias) v += bias[colj];
                C[row * (size_t)N + colj] = v;
            }
        }
    }
}

// ---------------------------------------------------------------------------
// Persistent recurrent kernel.
// Cluster of 8 CTAs = one batch group of 16 rows. CTA c owns h-cols
// [32c,32c+32) and the matching z/r/c columns of Ueff (98 KB stationary in
// SMEM). h exchanged via L2-resident global double buffer + cluster barrier.
// 128 threads: tr=warp (4 rows each), tc=lane (1 h-col, 3 gate cols).
// ---------------------------------------------------------------------------
#define RNN_SMEM ((HID * RANKSUM + HID * 16) * 4)   // 98304 + 16384 = 114688 B

__device__ __forceinline__ float sigmoidf_(float x)
{
    return __fdividef(1.f, 1.f + __expf(-x));
}
__device__ __forceinline__ float tanhf_(float x)
{
    return __fdividef(2.f, 1.f + __expf(-2.f * x)) - 1.f;
}

__global__ void __cluster_dims__(8, 1, 1) __launch_bounds__(128, 1)
rnn_kernel(const float* __restrict__ Ueff,   // [256,768] this layer
           const float* __restrict__ wx,     // [B*T,768]
           float* __restrict__ out_x,        // [B*T,256]
           float* __restrict__ hT_out,       // out + OUT0 + l*256, idx b*512+col
           float* __restrict__ hbuf)         // g_h
{
    extern __shared__ float smem[];
    float* sUs = smem;                  // [256][96]
    float* sh  = smem + HID * RANKSUM;  // [256][16]  (h[k][b])

    const int c  = blockIdx.x & 7;      // column group (== cluster rank)
    const int g  = blockIdx.x >> 3;     // batch group
    const int tid = threadIdx.x;
    const int tr = tid >> 5, tc = tid & 31;

    // Stationary Ueff slice: cols {c*32+tc, 256+c*32+tc, 512+c*32+tc}
    for (int idx = tid; idx < HID * RANKSUM; idx += 128) {
        int k = idx / RANKSUM, j = idx - k * RANKSUM;
        int gcol = ((j >> 5) << 8) + (c << 5) + (j & 31);
        sUs[idx] = Ueff[k * G3 + gcol];
    }
    // h0 = 0
    for (int i4 = tid; i4 < (HID * 16) / 4; i4 += 128)
        ((float4*)sh)[i4] = make_float4(0.f, 0.f, 0.f, 0.f);
    __syncthreads();

    const int col = (c << 5) + tc;      // owned h column
    const int b0  = g << 4;             // first batch row of group

    for (int t = 0; t < SEQ; ++t) {
        // wx loads first (independent of h -> hide DRAM latency under GEMM)
        float wz[4], wr[4], wc[4];
#pragma unroll
        for (int i = 0; i < 4; ++i) {
            const float* p = wx + ((size_t)(b0 + (tr << 2) + i) * SEQ + t) * G3 + col;
            wz[i] = p[0]; wr[i] = p[256]; wc[i] = p[512];
        }

        // uh[b, {z,r,c} col] = sum_k h[k][b] * Us[k][...]
        float az[4] = {0.f, 0.f, 0.f, 0.f};
        float ar[4] = {0.f, 0.f, 0.f, 0.f};
        float ac[4] = {0.f, 0.f, 0.f, 0.f};
#pragma unroll 8
        for (int k = 0; k < HID; ++k) {
            const float4 hv = *(const float4*)(sh + (k << 4) + (tr << 2));
            const float* urow = sUs + k * RANKSUM + tc;
            const float uz = urow[0], ur = urow[32], uc = urow[64];
            az[0] = fmaf(hv.x, uz, az[0]); az[1] = fmaf(hv.y, uz, az[1]);
            az[2] = fmaf(hv.z, uz, az[2]); az[3] = fmaf(hv.w, uz, az[3]);
            ar[0] = fmaf(hv.x, ur, ar[0]); ar[1] = fmaf(hv.y, ur, ar[1]);
            ar[2] = fmaf(hv.z, ur, ar[2]); ar[3] = fmaf(hv.w, ur, ar[3]);
            ac[0] = fmaf(hv.x, uc, ac[0]); ac[1] = fmaf(hv.y, uc, ac[1]);
            ac[2] = fmaf(hv.z, uc, ac[2]); ac[3] = fmaf(hv.w, uc, ac[3]);
        }

        // gates + h update (thread fully owns (4 rows) x (1 h-col))
        float hn[4];
#pragma unroll
        for (int i = 0; i < 4; ++i) {
            const int rl = (tr << 2) + i;
            const float hpv = sh[(col << 4) + rl];
            const float z = sigmoidf_(wz[i] + az[i]);
            const float r = sigmoidf_(wr[i] + ar[i]);
            const float cc = tanhf_(wc[i] + r * ac[i]);
            hn[i] = z * hpv + (1.f - z) * cc;
            out_x[((size_t)(b0 + rl) * SEQ + t) * HID + col] = hn[i];
            if (t == SEQ - 1)
                hT_out[(size_t)(b0 + rl) * 512 + col] = hn[i];
        }

        // publish h_{t+1} slice to the group double buffer
        const int nb = (t + 1) & 1;
        float* hg = hbuf + (((size_t)nb * 16 + g) * HID + col) * 16 + (tr << 2);
        *(float4*)hg = make_float4(hn[0], hn[1], hn[2], hn[3]);

        // cluster barrier (release/acquire: global writes visible to peers)
        asm volatile("barrier.cluster.arrive.aligned;" ::: "memory");
        asm volatile("barrier.cluster.wait.aligned;" ::: "memory");

        // reload full h_{t+1} for this group into SMEM
        const float4* src = (const float4*)(hbuf + ((size_t)nb * 16 + g) * HID * 16);
#pragma unroll
        for (int i4 = tid; i4 < (HID * 16) / 4; i4 += 128)
            ((float4*)sh)[i4] = src[i4];
        __syncthreads();
    }
}

// ---------------------------------------------------------------------------
// Launch
// ---------------------------------------------------------------------------
extern "C" void kernel_launch(void* const* d_in, const int* in_sizes, int n_in,
                              void* d_out, int out_size)
{
    const float* x   = (const float*)d_in[0];
    const float* Wd  = (const float*)d_in[1];
    const float* Wdg = (const float*)d_in[2];
    const float* Wo  = (const float*)d_in[3];
    const float* Wog = (const float*)d_in[4];
    const float* Ud  = (const float*)d_in[5];
    const float* Udg = (const float*)d_in[6];
    const float* Uo  = (const float*)d_in[7];
    const float* Uog = (const float*)d_in[8];
    const float* bb  = (const float*)d_in[9];
    float* out = (float*)d_out;

    float *pT, *pWX, *pX1, *pP, *pQ, *pPu, *pQu, *pUeff, *pH;
    cudaGetSymbolAddress((void**)&pT,   g_t_buf);
    cudaGetSymbolAddress((void**)&pWX,  g_wx_buf);
    cudaGetSymbolAddress((void**)&pX1,  g_x1);
    cudaGetSymbolAddress((void**)&pP,   g_P);
    cudaGetSymbolAddress((void**)&pQ,   g_Q);
    cudaGetSymbolAddress((void**)&pPu,  g_Pu);
    cudaGetSymbolAddress((void**)&pQu,  g_Qu);
    cudaGetSymbolAddress((void**)&pUeff, g_Ueff);
    cudaGetSymbolAddress((void**)&pH,   g_h);

    cudaFuncSetAttribute(rnn_kernel, cudaFuncAttributeMaxDynamicSharedMemorySize, RNN_SMEM);

    // 1. pack low-rank factors
    pack_kernel<<<(LAYERS * RANKSUM * G3 + 255) / 256, 256>>>(Wd, Wdg, Wo, Wog,
                                                              Ud, Udg, Uo, Uog);
    // 2. dense recurrent weights: Ueff[l] = Pu[l] @ Qu[l]  (256x768, K=96)
    for (int l = 0; l < LAYERS; ++l)
        gemm_tiled<<<dim3(HID / 64, G3 / 64), 256>>>(
            pPu + (size_t)l * HID * RANKSUM, pQu + (size_t)l * RANKSUM * G3,
            nullptr, pUeff + (size_t)l * HID * G3, HID, G3, RANKSUM);

    const size_t OUT0 = (size_t)ROWS * HID;   // 33,554,432

    for (int l = 0; l < LAYERS; ++l) {
        const float* xin = (l == 0) ? x : pX1;
        // 3. stage-1: T = x @ [Wd|Wo]   (131072 x 96, K=256)
        gemm_tiled<<<dim3(ROWS / 64, 2), 256>>>(
            xin, pP + (size_t)l * NIN * RANKSUM, nullptr, pT, ROWS, RANKSUM, NIN);
        // 4. stage-2: wx = T @ [Wdg;Wog] + b   (131072 x 768, K=96)
        gemm_tiled<<<dim3(ROWS / 64, G3 / 64), 256>>>(
            pT, pQ + (size_t)l * RANKSUM * G3, bb + l * G3, pWX, ROWS, G3, RANKSUM);
        // 5. sequential scan (persistent cluster kernel)
        float* ox = (l == LAYERS - 1) ? out : pX1;
        rnn_kernel<<<128, 128, RNN_SMEM>>>(
            pUeff + (size_t)l * HID * G3, pWX, ox, out + OUT0 + l * HID, pH);
    }
}